// round 14
// baseline (speedup 1.0000x reference)
#include <cuda_runtime.h>
#include <cuda_fp16.h>
#include <cstdint>

#define NB 16
#define NC 64          // C_IN == C_OUT == 64
#define VIN 40962
#define VOUT 163842

// Scratch: y[b][u][o] in fp16, rows of 128B. 84 MB.
__device__ __align__(256) __half g_y[(size_t)NB * VIN * NC];
// 1 if idx buffer is int64, 0 if int32.
__device__ int g_idx_is64;

static __device__ __forceinline__ uint32_t pack_h2(float a, float b) {
    __half2 h = __floats2half2_rn(a, b);
    return *(uint32_t*)&h;
}

static __device__ __forceinline__ void mma16816(float* d, const uint32_t* a,
                                                uint32_t b0, uint32_t b1) {
    asm volatile(
        "mma.sync.aligned.m16n8k16.row.col.f32.f16.f16.f32 "
        "{%0,%1,%2,%3}, {%4,%5,%6,%7}, {%8,%9}, {%0,%1,%2,%3};"
        : "+f"(d[0]), "+f"(d[1]), "+f"(d[2]), "+f"(d[3])
        : "r"(a[0]), "r"(a[1]), "r"(a[2]), "r"(a[3]), "r"(b0), "r"(b1));
}

// ---------------------------------------------------------------------------
// Stage 1 v3: y[b,u,o] = sum_c x[b,c,u] W[o,c]  (HMMA m16n8k16, f32 acc)
// 256 threads, tile 128u x 64o. acc[4][4] (two o-passes) -> 5+ blocks/SM.
// xs XOR-swizzled: conflict-free fill STS and A-fragment LDS.
// Warp-local epilogue (no block syncs) via per-warp staging buffer.
// ---------------------------------------------------------------------------
__global__ __launch_bounds__(256, 5)
void stage1_mma(const float* __restrict__ x, const float* __restrict__ W,
                const void* __restrict__ idx_raw) {
    __shared__ uint32_t xs[128][32];      // [u][cp ^ 4*(u&7)]  16 KB
    __shared__ uint2    wbf[8][4][32];    // [nt][kt][lane] B fragments  8 KB
    __shared__ uint32_t ws[8][16][20];    // per-warp epi staging  10.2 KB

    const int b   = blockIdx.y;
    const int u0  = blockIdx.x * 128;
    const int tid = threadIdx.x;
    const int lane = tid & 31, wid = tid >> 5;
    const int g = lane >> 2, t = lane & 3;

    if (b == 0 && blockIdx.x == 0 && tid == 0) {
        const int* p = (const int*)idx_raw;
        int all_odd_zero = 1;
#pragma unroll
        for (int k = 0; k < 8; k++)
            if (p[2 * k + 1] != 0) all_odd_zero = 0;
        g_idx_is64 = all_odd_zero;
    }

    // ---- W fragments (R12-proven layout) ----
#pragma unroll
    for (int i = tid; i < 8 * 4 * 32; i += 256) {
        const int nt = i >> 7, kt = (i >> 5) & 3, ln = i & 31;
        const int o   = nt * 8 + (ln >> 2);
        const int cp0 = kt * 8 + (ln & 3);
        float2 wlo = *(const float2*)&W[o * 64 + cp0 * 2];
        float2 whi = *(const float2*)&W[o * 64 + (cp0 + 4) * 2];
        wbf[nt][kt][ln] = make_uint2(pack_h2(wlo.x, wlo.y), pack_h2(whi.x, whi.y));
    }

    // ---- x fill: warp covers 8 cp x 4 u-pairs per step; sector-perfect LDG,
    //      conflict-free swizzled STS. ----
    {
        const int cpl  = lane >> 2;   // 0..7
        const int up_l = lane & 3;    // 0..3
        const int lim  = VIN - u0;    // valid u count in this tile (even)
        const float* xb = x + (size_t)b * NC * VIN + u0;
#pragma unroll
        for (int k = 0; k < 8; k++) {
            const int combo = wid * 8 + k;       // 0..63
            const int cpi = combo >> 4;          // 0..3
            const int upi = combo & 15;          // 0..15
            const int cp  = cpi * 8 + cpl;       // 0..31
            const int uA  = 8 * upi + 2 * up_l;  // 0..126 even
            float2 v0 = make_float2(0.f, 0.f), v1 = v0;
            if (uA < lim) {
                const float* p0 = xb + (size_t)(2 * cp) * VIN;
                v0 = __ldcs((const float2*)(p0 + uA));
                v1 = __ldcs((const float2*)(p0 + VIN + uA));
            }
            xs[uA][cp ^ (4 * (uA & 7))]             = pack_h2(v0.x, v1.x);
            xs[uA + 1][cp ^ (4 * ((uA + 1) & 7))]   = pack_h2(v0.y, v1.y);
        }
    }
    __syncthreads();

    const int ub = wid * 16;
    uint8_t* ybase = (uint8_t*)(g_y + (size_t)b * VIN * NC + (size_t)u0 * NC);

#pragma unroll
    for (int op = 0; op < 2; op++) {
        float acc[4][4];
#pragma unroll
        for (int n4 = 0; n4 < 4; n4++)
#pragma unroll
            for (int r = 0; r < 4; r++) acc[n4][r] = 0.0f;

#pragma unroll
        for (int kt = 0; kt < 4; kt++) {
            const int c0 = kt * 8 + t, c1 = kt * 8 + 4 + t;
            uint32_t a[4];
            a[0] = xs[ub + g][c0 ^ (4 * g)];        // (ub+g)&7 == g
            a[1] = xs[ub + 8 + g][c0 ^ (4 * g)];
            a[2] = xs[ub + g][c1 ^ (4 * g)];
            a[3] = xs[ub + 8 + g][c1 ^ (4 * g)];
#pragma unroll
            for (int n4 = 0; n4 < 4; n4++) {
                uint2 bb = wbf[op * 4 + n4][kt][lane];
                mma16816(acc[n4], a, bb.x, bb.y);
            }
        }

        // warp-local staging: rows g, g+8; half2 word w = n4*4 + t
#pragma unroll
        for (int n4 = 0; n4 < 4; n4++) {
            ws[wid][g][n4 * 4 + t]     = pack_h2(acc[n4][0], acc[n4][1]);
            ws[wid][g + 8][n4 * 4 + t] = pack_h2(acc[n4][2], acc[n4][3]);
        }
        __syncwarp();

        // warp-local copy-out: 16 rows x 16 words = 64 uint4 chunks, 2/lane
#pragma unroll
        for (int h = 0; h < 2; h++) {
            const int c   = h * 32 + lane;   // 0..63
            const int row = c >> 2, q = c & 3;
            const int ug  = ub + row;
            if (u0 + ug < VIN) {
                uint4 v = *(const uint4*)&ws[wid][row][q * 4];
                *(uint4*)(ybase + (size_t)ug * 128 + op * 64 + q * 16) = v;
            }
        }
        __syncwarp();   // before pass-1 overwrites ws
    }
}

// ---------------------------------------------------------------------------
// Stage 2 (R12-exact): out[b,o,v] = 0.5*(y[i0]+y[i1]) + bias[o]
// ---------------------------------------------------------------------------
__global__ __launch_bounds__(256)
void stage2_gather(const void* __restrict__ idx_raw,
                   const float* __restrict__ bias,
                   float* __restrict__ out) {
    __shared__ float t2[64][65];
    __shared__ float bs[64];

    const int b    = blockIdx.y;
    const int v0   = blockIdx.x * 64;
    const int tid  = threadIdx.x;
    const int lane = tid & 31;
    const int w    = tid >> 5;
    const int is64 = g_idx_is64;

    if (tid < 64) bs[tid] = bias[tid];

    const __half* yb = g_y + (size_t)b * VIN * NC;

    const int g = lane >> 3;      // vertex within quad
    const int s = lane & 7;       // 16B chunk within 128B row
#pragma unroll
    for (int it = 0; it < 2; it++) {
        const int vl = w * 8 + it * 4 + g;
        const int v  = v0 + vl;
        if (v < VOUT) {
            long long i0, i1;
            if (is64) {
                longlong2 p = *((const longlong2*)idx_raw + v);
                i0 = p.x; i1 = p.y;
            } else {
                int2 p = *((const int2*)idx_raw + v);
                i0 = p.x; i1 = p.y;
            }
            i0 = i0 < 0 ? 0 : (i0 >= VIN ? VIN - 1 : i0);
            i1 = i1 < 0 ? 0 : (i1 >= VIN ? VIN - 1 : i1);
            union { uint4 u; __half2 h[4]; } A, B;
            A.u = *(const uint4*)(yb + (size_t)i0 * NC + s * 8);
            B.u = *(const uint4*)(yb + (size_t)i1 * NC + s * 8);
            float* trow = &t2[vl][s * 8];
#pragma unroll
            for (int k = 0; k < 4; k++) {
                float2 fa = __half22float2(A.h[k]);
                float2 fb = __half22float2(B.h[k]);
                trow[2 * k + 0] = 0.5f * (fa.x + fb.x);
                trow[2 * k + 1] = 0.5f * (fa.y + fb.y);
            }
        }
    }
    __syncthreads();

    {
        const int vA = v0 + lane;
        const int vB = vA + 32;
        float* ob = out + (size_t)b * NC * VOUT;
#pragma unroll
        for (int j = 0; j < 8; j++) {
            const int o  = w * 8 + j;
            const float bo = bs[o];
            float* orow = ob + (size_t)o * VOUT;
            if (vA < VOUT) __stcs(orow + vA, t2[lane][o] + bo);
            if (vB < VOUT) __stcs(orow + vB, t2[lane + 32][o] + bo);
        }
    }
}

// ---------------------------------------------------------------------------
extern "C" void kernel_launch(void* const* d_in, const int* in_sizes, int n_in,
                              void* d_out, int out_size) {
    const float* x = nullptr;
    const void*  idx = nullptr;
    const float* W = nullptr;
    const float* bias = nullptr;
    for (int i = 0; i < n_in; i++) {
        switch (in_sizes[i]) {
            case 41945088: x    = (const float*)d_in[i]; break;  // 16*64*40962
            case 327684:   idx  = d_in[i];               break;  // 163842*2
            case 4096:     W    = (const float*)d_in[i]; break;  // 64*64
            case 64:       bias = (const float*)d_in[i]; break;  // 64
            default: break;
        }
    }
    float* out = (float*)d_out;
    (void)out_size;

    dim3 g1((VIN + 127) / 128, NB);
    stage1_mma<<<g1, 256>>>(x, W, idx);

    dim3 g2((VOUT + 63) / 64, NB);
    stage2_gather<<<g2, 256>>>(idx, bias, out);
}

// round 15
// speedup vs baseline: 1.0680x; 1.0680x over previous
#include <cuda_runtime.h>
#include <cuda_fp16.h>
#include <cstdint>

#define NB 16
#define NC 64          // C_IN == C_OUT == 64
#define VIN 40962
#define VOUT 163842

// Scratch: y[b][u][o] in fp16, rows of 128B. 84 MB.
__device__ __half g_y[(size_t)NB * VIN * NC];
// 1 if idx buffer is int64, 0 if int32.
__device__ int g_idx_is64;

static __device__ __forceinline__ uint32_t pack_h2(float a, float b) {
    __half2 h = __floats2half2_rn(a, b);
    return *(uint32_t*)&h;
}

static __device__ __forceinline__ void mma16816(float* d, const uint32_t* a,
                                                uint32_t b0, uint32_t b1) {
    asm volatile(
        "mma.sync.aligned.m16n8k16.row.col.f32.f16.f16.f32 "
        "{%0,%1,%2,%3}, {%4,%5,%6,%7}, {%8,%9}, {%0,%1,%2,%3};"
        : "+f"(d[0]), "+f"(d[1]), "+f"(d[2]), "+f"(d[3])
        : "r"(a[0]), "r"(a[1]), "r"(a[2]), "r"(a[3]), "r"(b0), "r"(b1));
}

// ---------------------------------------------------------------------------
// Stage 1 (R12-exact): y[b,u,o] = sum_c x[b,c,u] W[o,c]  (HMMA, f32 acc)
// 256 threads, tile 128u x 64o; warp w covers u strip [w*16, w*16+16).
// W staged in FRAGMENT layout (conflict-free LDS.64 in mainloop).
// ---------------------------------------------------------------------------
__global__ __launch_bounds__(256, 4)
void stage1_mma(const float* __restrict__ x, const float* __restrict__ W,
                const void* __restrict__ idx_raw) {
    __shared__ uint32_t xs[128][33];     // [u][cp] half2(x[2cp][u], x[2cp+1][u])
    __shared__ uint2    wbf[8][4][32];   // [nt][kt][lane] = {b0, b1}  (8 KB)

    const int b   = blockIdx.y;
    const int u0  = blockIdx.x * 128;
    const int tid = threadIdx.x;

    if (b == 0 && blockIdx.x == 0 && tid == 0) {
        const int* p = (const int*)idx_raw;
        int all_odd_zero = 1;
#pragma unroll
        for (int k = 0; k < 8; k++)
            if (p[2 * k + 1] != 0) all_odd_zero = 0;
        g_idx_is64 = all_odd_zero;
    }

    // ---- W fragments: wbf[nt][kt][lane] = { b0, b1 } for the m16n8k16 B-frag
#pragma unroll
    for (int i = tid; i < 8 * 4 * 32; i += 256) {
        const int nt = i >> 7, kt = (i >> 5) & 3, ln = i & 31;
        const int o   = nt * 8 + (ln >> 2);
        const int cp0 = kt * 8 + (ln & 3);
        float2 wlo = *(const float2*)&W[o * 64 + cp0 * 2];
        float2 whi = *(const float2*)&W[o * 64 + (cp0 + 4) * 2];
        wbf[nt][kt][ln] = make_uint2(pack_h2(wlo.x, wlo.y), pack_h2(whi.x, whi.y));
    }

    // ---- x tile fill ----
    const float* xb = x + (size_t)b * NC * VIN + u0;
    if (u0 + 128 <= VIN) {
#pragma unroll
        for (int i = tid; i < 32 * 64; i += 256) {
            int cp = i >> 6, up = i & 63;
            const float* p0 = xb + (size_t)(2 * cp) * VIN;
            float2 v0 = __ldcs((const float2*)(p0 + 2 * up));
            float2 v1 = __ldcs((const float2*)(p0 + VIN + 2 * up));
            xs[2 * up][cp]     = pack_h2(v0.x, v1.x);
            xs[2 * up + 1][cp] = pack_h2(v0.y, v1.y);
        }
    } else {
        for (int i = tid; i < 32 * 64; i += 256) {
            int cp = i >> 6, up = i & 63;
            const float* p0 = xb + (size_t)(2 * cp) * VIN;
            int uA = 2 * up, uB = 2 * up + 1;
            float a0 = (u0 + uA < VIN) ? p0[uA] : 0.0f;
            float a1 = (u0 + uA < VIN) ? p0[VIN + uA] : 0.0f;
            float b0f = (u0 + uB < VIN) ? p0[uB] : 0.0f;
            float b1f = (u0 + uB < VIN) ? p0[VIN + uB] : 0.0f;
            xs[uA][cp] = pack_h2(a0, a1);
            xs[uB][cp] = pack_h2(b0f, b1f);
        }
    }
    __syncthreads();

    const int lane = tid & 31, wid = tid >> 5;   // 8 warps
    const int g = lane >> 2, t = lane & 3;
    const int ub = wid * 16;

    float acc[8][4];
#pragma unroll
    for (int nt = 0; nt < 8; nt++)
#pragma unroll
        for (int r = 0; r < 4; r++) acc[nt][r] = 0.0f;

#pragma unroll
    for (int kt = 0; kt < 4; kt++) {
        uint32_t a[4];
        a[0] = xs[ub + g][kt * 8 + t];
        a[1] = xs[ub + 8 + g][kt * 8 + t];
        a[2] = xs[ub + g][kt * 8 + 4 + t];
        a[3] = xs[ub + 8 + g][kt * 8 + 4 + t];
#pragma unroll
        for (int nt = 0; nt < 8; nt++) {
            uint2 bb = wbf[nt][kt][lane];   // conflict-free LDS.64
            mma16816(acc[nt], a, bb.x, bb.y);
        }
    }

    __syncthreads();
    uint32_t* ys = (uint32_t*)xs;   // [u][32 half2 words], stride 33
    {
        int r0 = ub + g;
#pragma unroll
        for (int nt = 0; nt < 8; nt++) {
            ys[r0 * 33 + nt * 4 + t]       = pack_h2(acc[nt][0], acc[nt][1]);
            ys[(r0 + 8) * 33 + nt * 4 + t] = pack_h2(acc[nt][2], acc[nt][3]);
        }
    }
    __syncthreads();

    __half* yb = g_y + (size_t)b * VIN * NC;
#pragma unroll
    for (int i = tid; i < 128 * 8; i += 256) {
        int u = i >> 3, q = i & 7;
        if (u0 + u < VIN) {
            const uint32_t* row = ys + u * 33 + q * 4;
            uint4 v = make_uint4(row[0], row[1], row[2], row[3]);
            *(uint4*)&yb[(size_t)(u0 + u) * NC + q * 8] = v;
        }
    }
}

// ---------------------------------------------------------------------------
// Stage 2 (R12 + __ldcg gather): out[b,o,v] = 0.5*(y[i0]+y[i1]) + bias[o]
// Gather loads bypass L1 (.cg): random 128B rows have ~zero per-SM reuse.
// ---------------------------------------------------------------------------
__global__ __launch_bounds__(256)
void stage2_gather(const void* __restrict__ idx_raw,
                   const float* __restrict__ bias,
                   float* __restrict__ out) {
    __shared__ float t[64][65];
    __shared__ float bs[64];

    const int b    = blockIdx.y;
    const int v0   = blockIdx.x * 64;
    const int tid  = threadIdx.x;
    const int lane = tid & 31;
    const int w    = tid >> 5;
    const int is64 = g_idx_is64;

    if (tid < 64) bs[tid] = bias[tid];

    const __half* yb = g_y + (size_t)b * VIN * NC;

    const int g = lane >> 3;      // vertex within quad
    const int s = lane & 7;       // 16B chunk within 128B row
#pragma unroll
    for (int it = 0; it < 2; it++) {
        const int vl = w * 8 + it * 4 + g;
        const int v  = v0 + vl;
        if (v < VOUT) {
            long long i0, i1;
            if (is64) {
                longlong2 p = *((const longlong2*)idx_raw + v);
                i0 = p.x; i1 = p.y;
            } else {
                int2 p = *((const int2*)idx_raw + v);
                i0 = p.x; i1 = p.y;
            }
            i0 = i0 < 0 ? 0 : (i0 >= VIN ? VIN - 1 : i0);
            i1 = i1 < 0 ? 0 : (i1 >= VIN ? VIN - 1 : i1);
            union { uint4 u; __half2 h[4]; } A, B;
            A.u = __ldcg((const uint4*)(yb + (size_t)i0 * NC + s * 8));
            B.u = __ldcg((const uint4*)(yb + (size_t)i1 * NC + s * 8));
            float* trow = &t[vl][s * 8];
#pragma unroll
            for (int k = 0; k < 4; k++) {
                float2 fa = __half22float2(A.h[k]);
                float2 fb = __half22float2(B.h[k]);
                trow[2 * k + 0] = 0.5f * (fa.x + fb.x);
                trow[2 * k + 1] = 0.5f * (fa.y + fb.y);
            }
        }
    }
    __syncthreads();

    {
        const int vA = v0 + lane;
        const int vB = vA + 32;
        float* ob = out + (size_t)b * NC * VOUT;
#pragma unroll
        for (int j = 0; j < 8; j++) {
            const int o  = w * 8 + j;
            const float bo = bs[o];
            float* orow = ob + (size_t)o * VOUT;
            if (vA < VOUT) __stcs(orow + vA, t[lane][o] + bo);
            if (vB < VOUT) __stcs(orow + vB, t[lane + 32][o] + bo);
        }
    }
}

// ---------------------------------------------------------------------------
extern "C" void kernel_launch(void* const* d_in, const int* in_sizes, int n_in,
                              void* d_out, int out_size) {
    const float* x = nullptr;
    const void*  idx = nullptr;
    const float* W = nullptr;
    const float* bias = nullptr;
    for (int i = 0; i < n_in; i++) {
        switch (in_sizes[i]) {
            case 41945088: x    = (const float*)d_in[i]; break;  // 16*64*40962
            case 327684:   idx  = d_in[i];               break;  // 163842*2
            case 4096:     W    = (const float*)d_in[i]; break;  // 64*64
            case 64:       bias = (const float*)d_in[i]; break;  // 64
            default: break;
        }
    }
    float* out = (float*)d_out;
    (void)out_size;

    dim3 g1((VIN + 127) / 128, NB);
    stage1_mma<<<g1, 256>>>(x, W, idx);

    dim3 g2((VOUT + 63) / 64, NB);
    stage2_gather<<<g2, 256>>>(idx, bias, out);
}

// round 16
// speedup vs baseline: 1.0970x; 1.0272x over previous
#include <cuda_runtime.h>
#include <cuda_fp16.h>
#include <cstdint>

#define NB 16
#define NC 64          // C_IN == C_OUT == 64
#define VIN 40962
#define VOUT 163842

// Scratch: y[b][u][o] in fp16, rows of 128B. 84 MB.
__device__ __half g_y[(size_t)NB * VIN * NC];
// 1 if idx buffer is int64, 0 if int32.
__device__ int g_idx_is64;

static __device__ __forceinline__ uint32_t pack_h2(float a, float b) {
    __half2 h = __floats2half2_rn(a, b);
    return *(uint32_t*)&h;
}

static __device__ __forceinline__ void mma16816(float* d, const uint32_t* a,
                                                uint32_t b0, uint32_t b1) {
    asm volatile(
        "mma.sync.aligned.m16n8k16.row.col.f32.f16.f16.f32 "
        "{%0,%1,%2,%3}, {%4,%5,%6,%7}, {%8,%9}, {%0,%1,%2,%3};"
        : "+f"(d[0]), "+f"(d[1]), "+f"(d[2]), "+f"(d[3])
        : "r"(a[0]), "r"(a[1]), "r"(a[2]), "r"(a[3]), "r"(b0), "r"(b1));
}

// ---------------------------------------------------------------------------
// Stage 1 (R12 layout, 2 tiles/block): y[b,u,o] = sum_c x[b,c,u] W[o,c]
// 256 threads. Per block: W fragments built ONCE, then two 128u x 64o tiles.
// ---------------------------------------------------------------------------
__global__ __launch_bounds__(256, 4)
void stage1_mma(const float* __restrict__ x, const float* __restrict__ W,
                const void* __restrict__ idx_raw) {
    __shared__ uint32_t xs[128][33];     // [u][cp] half2(x[2cp][u], x[2cp+1][u])
    __shared__ uint2    wbf[8][4][32];   // [nt][kt][lane] = {b0, b1}  (8 KB)

    const int b   = blockIdx.y;
    const int u0b = blockIdx.x * 256;
    const int tid = threadIdx.x;
    const int lane = tid & 31, wid = tid >> 5;   // 8 warps
    const int g = lane >> 2, t = lane & 3;
    const int ub = wid * 16;

    if (b == 0 && blockIdx.x == 0 && tid == 0) {
        const int* p = (const int*)idx_raw;
        int all_odd_zero = 1;
#pragma unroll
        for (int k = 0; k < 8; k++)
            if (p[2 * k + 1] != 0) all_odd_zero = 0;
        g_idx_is64 = all_odd_zero;
    }

    // ---- W fragments (once per block) ----
#pragma unroll
    for (int i = tid; i < 8 * 4 * 32; i += 256) {
        const int nt = i >> 7, kt = (i >> 5) & 3, ln = i & 31;
        const int o   = nt * 8 + (ln >> 2);
        const int cp0 = kt * 8 + (ln & 3);
        float2 wlo = *(const float2*)&W[o * 64 + cp0 * 2];
        float2 whi = *(const float2*)&W[o * 64 + (cp0 + 4) * 2];
        wbf[nt][kt][ln] = make_uint2(pack_h2(wlo.x, wlo.y), pack_h2(whi.x, whi.y));
    }

    const float* xbase = x + (size_t)b * NC * VIN;
    __half* ybbase = g_y + (size_t)b * VIN * NC;

#pragma unroll
    for (int tp = 0; tp < 2; tp++) {
        const int u0 = u0b + tp * 128;
        if (u0 >= VIN) break;

        // ---- x tile fill ----
        const float* xb = xbase + u0;
        if (u0 + 128 <= VIN) {
#pragma unroll
            for (int i = tid; i < 32 * 64; i += 256) {
                int cp = i >> 6, up = i & 63;
                const float* p0 = xb + (size_t)(2 * cp) * VIN;
                float2 v0 = __ldcs((const float2*)(p0 + 2 * up));
                float2 v1 = __ldcs((const float2*)(p0 + VIN + 2 * up));
                xs[2 * up][cp]     = pack_h2(v0.x, v1.x);
                xs[2 * up + 1][cp] = pack_h2(v0.y, v1.y);
            }
        } else {
            for (int i = tid; i < 32 * 64; i += 256) {
                int cp = i >> 6, up = i & 63;
                const float* p0 = xb + (size_t)(2 * cp) * VIN;
                int uA = 2 * up, uB = 2 * up + 1;
                float a0 = (u0 + uA < VIN) ? p0[uA] : 0.0f;
                float a1 = (u0 + uA < VIN) ? p0[VIN + uA] : 0.0f;
                float b0f = (u0 + uB < VIN) ? p0[uB] : 0.0f;
                float b1f = (u0 + uB < VIN) ? p0[VIN + uB] : 0.0f;
                xs[uA][cp] = pack_h2(a0, a1);
                xs[uB][cp] = pack_h2(b0f, b1f);
            }
        }
        __syncthreads();

        // ---- mainloop ----
        float acc[8][4];
#pragma unroll
        for (int nt = 0; nt < 8; nt++)
#pragma unroll
            for (int r = 0; r < 4; r++) acc[nt][r] = 0.0f;

#pragma unroll
        for (int kt = 0; kt < 4; kt++) {
            uint32_t a[4];
            a[0] = xs[ub + g][kt * 8 + t];
            a[1] = xs[ub + 8 + g][kt * 8 + t];
            a[2] = xs[ub + g][kt * 8 + 4 + t];
            a[3] = xs[ub + 8 + g][kt * 8 + 4 + t];
#pragma unroll
            for (int nt = 0; nt < 8; nt++) {
                uint2 bb = wbf[nt][kt][lane];   // conflict-free LDS.64
                mma16816(acc[nt], a, bb.x, bb.y);
            }
        }

        __syncthreads();   // everyone done reading xs before staging reuse
        uint32_t* ys = (uint32_t*)xs;   // [u][32 half2 words], stride 33
        {
            int r0 = ub + g;
#pragma unroll
            for (int nt = 0; nt < 8; nt++) {
                ys[r0 * 33 + nt * 4 + t]       = pack_h2(acc[nt][0], acc[nt][1]);
                ys[(r0 + 8) * 33 + nt * 4 + t] = pack_h2(acc[nt][2], acc[nt][3]);
            }
        }
        __syncthreads();

        __half* yb = ybbase + (size_t)u0 * NC;
#pragma unroll
        for (int i = tid; i < 128 * 8; i += 256) {
            int u = i >> 3, q = i & 7;
            if (u0 + u < VIN) {
                const uint32_t* row = ys + u * 33 + q * 4;
                uint4 v = make_uint4(row[0], row[1], row[2], row[3]);
                *(uint4*)&yb[(size_t)u * NC + q * 8] = v;
            }
        }
        if (tp == 0) __syncthreads();   // copy-out reads ys before next fill
    }
}

// ---------------------------------------------------------------------------
// Stage 2 (R12-exact, plain loads): out[b,o,v] = 0.5*(y[i0]+y[i1]) + bias[o]
// ---------------------------------------------------------------------------
__global__ __launch_bounds__(256)
void stage2_gather(const void* __restrict__ idx_raw,
                   const float* __restrict__ bias,
                   float* __restrict__ out) {
    __shared__ float t[64][65];
    __shared__ float bs[64];

    const int b    = blockIdx.y;
    const int v0   = blockIdx.x * 64;
    const int tid  = threadIdx.x;
    const int lane = tid & 31;
    const int w    = tid >> 5;
    const int is64 = g_idx_is64;

    if (tid < 64) bs[tid] = bias[tid];

    const __half* yb = g_y + (size_t)b * VIN * NC;

    const int g = lane >> 3;      // vertex within quad
    const int s = lane & 7;       // 16B chunk within 128B row
#pragma unroll
    for (int it = 0; it < 2; it++) {
        const int vl = w * 8 + it * 4 + g;
        const int v  = v0 + vl;
        if (v < VOUT) {
            long long i0, i1;
            if (is64) {
                longlong2 p = *((const longlong2*)idx_raw + v);
                i0 = p.x; i1 = p.y;
            } else {
                int2 p = *((const int2*)idx_raw + v);
                i0 = p.x; i1 = p.y;
            }
            i0 = i0 < 0 ? 0 : (i0 >= VIN ? VIN - 1 : i0);
            i1 = i1 < 0 ? 0 : (i1 >= VIN ? VIN - 1 : i1);
            union { uint4 u; __half2 h[4]; } A, B;
            A.u = *(const uint4*)(yb + (size_t)i0 * NC + s * 8);
            B.u = *(const uint4*)(yb + (size_t)i1 * NC + s * 8);
            float* trow = &t[vl][s * 8];
#pragma unroll
            for (int k = 0; k < 4; k++) {
                float2 fa = __half22float2(A.h[k]);
                float2 fb = __half22float2(B.h[k]);
                trow[2 * k + 0] = 0.5f * (fa.x + fb.x);
                trow[2 * k + 1] = 0.5f * (fa.y + fb.y);
            }
        }
    }
    __syncthreads();

    {
        const int vA = v0 + lane;
        const int vB = vA + 32;
        float* ob = out + (size_t)b * NC * VOUT;
#pragma unroll
        for (int j = 0; j < 8; j++) {
            const int o  = w * 8 + j;
            const float bo = bs[o];
            float* orow = ob + (size_t)o * VOUT;
            if (vA < VOUT) __stcs(orow + vA, t[lane][o] + bo);
            if (vB < VOUT) __stcs(orow + vB, t[lane + 32][o] + bo);
        }
    }
}

// ---------------------------------------------------------------------------
extern "C" void kernel_launch(void* const* d_in, const int* in_sizes, int n_in,
                              void* d_out, int out_size) {
    const float* x = nullptr;
    const void*  idx = nullptr;
    const float* W = nullptr;
    const float* bias = nullptr;
    for (int i = 0; i < n_in; i++) {
        switch (in_sizes[i]) {
            case 41945088: x    = (const float*)d_in[i]; break;  // 16*64*40962
            case 327684:   idx  = d_in[i];               break;  // 163842*2
            case 4096:     W    = (const float*)d_in[i]; break;  // 64*64
            case 64:       bias = (const float*)d_in[i]; break;  // 64
            default: break;
        }
    }
    float* out = (float*)d_out;
    (void)out_size;

    dim3 g1((VIN + 255) / 256, NB);
    stage1_mma<<<g1, 256>>>(x, W, idx);

    dim3 g2((VOUT + 63) / 64, NB);
    stage2_gather<<<g2, 256>>>(idx, bias, out);
}